// round 15
// baseline (speedup 1.0000x reference)
#include <cuda_runtime.h>
#include <cuda_bf16.h>
#include <math.h>

#define LQ 4096
#define DIM 2048
#define NH 8
#define NKVH 2
#define HD 256
#define WIN 512

// fp32 intermediates
__device__ float g_q[(size_t)LQ * NH * HD];
__device__ float g_k[(size_t)LQ * NKVH * HD];
__device__ float g_v[(size_t)LQ * NKVH * HD];
__device__ float g_attn[(size_t)LQ * NH * HD];

// bf16 hi/lo split, k-pairs packed in uint32 (lower 16 = even k)
__device__ unsigned g_xh[(size_t)LQ * DIM / 2];
__device__ unsigned g_xl[(size_t)LQ * DIM / 2];
__device__ unsigned g_ah[(size_t)LQ * (NH * HD) / 2];
__device__ unsigned g_al[(size_t)LQ * (NH * HD) / 2];
// weights transposed to [N][K/2] packed
__device__ unsigned g_wqh[(size_t)(NH * HD) * DIM / 2];
__device__ unsigned g_wql[(size_t)(NH * HD) * DIM / 2];
__device__ unsigned g_wkh[(size_t)(NKVH * HD) * DIM / 2];
__device__ unsigned g_wkl[(size_t)(NKVH * HD) * DIM / 2];
__device__ unsigned g_wvh[(size_t)(NKVH * HD) * DIM / 2];
__device__ unsigned g_wvl[(size_t)(NKVH * HD) * DIM / 2];
__device__ unsigned g_woh[(size_t)DIM * (NH * HD) / 2];
__device__ unsigned g_wol[(size_t)DIM * (NH * HD) / 2];
// attention operands
__device__ unsigned g_qh[(size_t)LQ * NH * HD / 2];
__device__ unsigned g_ql[(size_t)LQ * NH * HD / 2];
__device__ unsigned g_kh[(size_t)LQ * NKVH * HD / 2];
__device__ unsigned g_kl[(size_t)LQ * NKVH * HD / 2];
__device__ unsigned g_vth[(size_t)NKVH * HD * LQ / 2];
__device__ unsigned g_vtl[(size_t)NKVH * HD * LQ / 2];

__device__ __forceinline__ unsigned pack2(__nv_bfloat16 a, __nv_bfloat16 b) {
    return (unsigned)__bfloat16_as_ushort(a) | ((unsigned)__bfloat16_as_ushort(b) << 16);
}

__device__ __forceinline__ void split2(float a, float b, unsigned& hi, unsigned& lo) {
    __nv_bfloat16 ha = __float2bfloat16_rn(a), hb = __float2bfloat16_rn(b);
    hi = pack2(ha, hb);
    lo = pack2(__float2bfloat16_rn(a - __bfloat162float(ha)),
               __float2bfloat16_rn(b - __bfloat162float(hb)));
}

__global__ __launch_bounds__(256) void splitpack(const float* __restrict__ src,
                                                 unsigned* __restrict__ hi,
                                                 unsigned* __restrict__ lo,
                                                 int npairs) {
    int i = blockIdx.x * 256 + threadIdx.x;
    if (i >= npairs) return;
    float2 v = ((const float2*)src)[i];
    unsigned h, l;
    split2(v.x, v.y, h, l);
    hi[i] = h; lo[i] = l;
}

__global__ __launch_bounds__(256) void wsplit(const float* __restrict__ W,
                                              unsigned* __restrict__ Wh,
                                              unsigned* __restrict__ Wl,
                                              int K, int N) {
    int idx = blockIdx.x * 256 + threadIdx.x;
    int total = N * (K >> 1);
    if (idx >= total) return;
    int i = idx / N;
    int n = idx % N;
    float a = W[(size_t)(2 * i) * N + n];
    float b = W[(size_t)(2 * i + 1) * N + n];
    unsigned h, l;
    split2(a, b, h, l);
    size_t o = (size_t)n * (K >> 1) + i;
    Wh[o] = h; Wl[o] = l;
}

// V [token][kvh][d] -> Vt hi/lo [kvh][d][token-pair] packed
__global__ __launch_bounds__(256) void vtsplit() {
    __shared__ float t[64][65];
    int t0 = blockIdx.x * 64;
    int d0 = blockIdx.y * 64;
    int kvh = blockIdx.z;
    int tid = threadIdx.x;
#pragma unroll
    for (int i = 0; i < 4; i++) {
        int idx = tid + i * 256;
        int tt = idx >> 4;
        int dd = (idx & 15) * 4;
        float4 v = *(const float4*)&g_v[((size_t)(t0 + tt) * NKVH + kvh) * HD + d0 + dd];
        t[tt][dd] = v.x; t[tt][dd + 1] = v.y; t[tt][dd + 2] = v.z; t[tt][dd + 3] = v.w;
    }
    __syncthreads();
#pragma unroll
    for (int i = 0; i < 8; i++) {
        int idx = tid + i * 256;
        int dd = idx >> 5;
        int tp = idx & 31;
        unsigned h, l;
        split2(t[2 * tp][dd], t[2 * tp + 1][dd], h, l);
        size_t o = ((size_t)(kvh * HD + d0 + dd)) * (LQ / 2) + (t0 >> 1) + tp;
        g_vth[o] = h; g_vtl[o] = l;
    }
}

__device__ __forceinline__ void mmabf(float* c, const unsigned* a, const unsigned* b) {
    asm volatile(
        "mma.sync.aligned.m16n8k16.row.col.f32.bf16.bf16.f32 "
        "{%0,%1,%2,%3},{%4,%5,%6,%7},{%8,%9},{%0,%1,%2,%3};"
        : "+f"(c[0]), "+f"(c[1]), "+f"(c[2]), "+f"(c[3])
        : "r"(a[0]), "r"(a[1]), "r"(a[2]), "r"(a[3]), "r"(b[0]), "r"(b[1]));
}

__device__ __forceinline__ void ldsm4(unsigned* d, unsigned saddr) {
    asm volatile("ldmatrix.sync.aligned.m8n8.x4.shared.b16 {%0,%1,%2,%3}, [%4];"
                 : "=r"(d[0]), "=r"(d[1]), "=r"(d[2]), "=r"(d[3]) : "r"(saddr));
}

// ---------------------------------------------------------------------------
// Error-compensated bf16 GEMM, ldmatrix fragment loads.
// ---------------------------------------------------------------------------
#define KTILE 32
#define KPAIR 16
#define BPAD 20
#define SMBUF (128 * BPAD)

__global__ __launch_bounds__(256) void bgemm(
    const unsigned* __restrict__ Agh, const unsigned* __restrict__ Agl, int K,
    const unsigned* __restrict__ Bh0, const unsigned* __restrict__ Bl0, float* __restrict__ C0, int N0, int t0,
    const unsigned* __restrict__ Bh1, const unsigned* __restrict__ Bl1, float* __restrict__ C1, int N1, int t1,
    const unsigned* __restrict__ Bh2, const unsigned* __restrict__ Bl2, float* __restrict__ C2, int N2) {
    extern __shared__ unsigned smu[];

    int tid = threadIdx.x;
    int lane = tid & 31;
    int w = tid >> 5;
    int g = lane >> 2;
    int r = lane & 3;
    int m_base = (w >> 2) * 64;
    int n_base = (w & 3) * 32;

    int m0 = blockIdx.y * 128;
    int bx = blockIdx.x;
    const unsigned *Bh, *Bl; float* C; int N, n0;
    if (bx < t0)           { Bh = Bh0; Bl = Bl0; C = C0; N = N0; n0 = bx * 128; }
    else if (bx < t0 + t1) { Bh = Bh1; Bl = Bl1; C = C1; N = N1; n0 = (bx - t0) * 128; }
    else                   { Bh = Bh2; Bl = Bl2; C = C2; N = N2; n0 = (bx - t0 - t1) * 128; }

    int Kp = K >> 1;
    int frow = tid >> 1;
    int fcu = (tid & 1) * 8;

    unsigned smbase = (unsigned)__cvta_generic_to_shared(smu);
    const unsigned* ga = Agh + (size_t)(m0 + frow) * Kp + fcu;
    const unsigned* gal = Agl + (size_t)(m0 + frow) * Kp + fcu;
    const unsigned* gb = Bh + (size_t)(n0 + frow) * Kp + fcu;
    const unsigned* gbl = Bl + (size_t)(n0 + frow) * Kp + fcu;
    unsigned sa_off = (frow * BPAD + fcu) * 4;

    // per-lane ldmatrix address components
    int lrow = lane & 15;             // row within 16-row group
    int lk = (lane & 16) ? 4 : 0;     // +4 kpairs for second k-half

#define CPA(mat_idx, buf, goff, gptr)                                        \
    {                                                                        \
        unsigned sp = smbase + ((mat_idx)*2 + (buf)) * SMBUF * 4 + sa_off;   \
        asm volatile("cp.async.cg.shared.global [%0], [%1], 16;" ::          \
                     "r"(sp), "l"((gptr) + (goff)));                         \
        asm volatile("cp.async.cg.shared.global [%0], [%1], 16;" ::          \
                     "r"(sp + 16), "l"((gptr) + (goff) + 4));                \
    }

    float acc[4][4][4];
#pragma unroll
    for (int i = 0; i < 4; i++)
#pragma unroll
        for (int j = 0; j < 4; j++)
#pragma unroll
            for (int q = 0; q < 4; q++) acc[i][j][q] = 0.0f;

    int ntiles = K / KTILE;

    CPA(0, 0, 0, ga); CPA(1, 0, 0, gal); CPA(2, 0, 0, gb); CPA(3, 0, 0, gbl);
    asm volatile("cp.async.commit_group;");

    for (int kt = 0; kt < ntiles; kt++) {
        int cur = kt & 1;
        bool more = (kt + 1) < ntiles;
        if (more) {
            int goff = (kt + 1) * KPAIR;
            int nb = cur ^ 1;
            CPA(0, nb, goff, ga); CPA(1, nb, goff, gal);
            CPA(2, nb, goff, gb); CPA(3, nb, goff, gbl);
            asm volatile("cp.async.commit_group;");
            asm volatile("cp.async.wait_group 1;");
        } else {
            asm volatile("cp.async.wait_group 0;");
        }
        __syncthreads();

        // shared byte base for each matrix buffer
        unsigned bAh = smbase + (0 * 2 + cur) * SMBUF * 4;
        unsigned bAl = smbase + (1 * 2 + cur) * SMBUF * 4;
        unsigned bBh = smbase + (2 * 2 + cur) * SMBUF * 4;
        unsigned bBl = smbase + (3 * 2 + cur) * SMBUF * 4;

#pragma unroll
        for (int ks = 0; ks < 2; ks++) {
            int kb = ks * 8 + lk;
            unsigned bh[4][2], bl[4][2];
#pragma unroll
            for (int ntp = 0; ntp < 2; ntp++) {
                unsigned off = ((n_base + ntp * 16 + lrow) * BPAD + kb) * 4;
                unsigned t[4];
                ldsm4(t, bBh + off);
                bh[2 * ntp][0] = t[0]; bh[2 * ntp + 1][0] = t[1];
                bh[2 * ntp][1] = t[2]; bh[2 * ntp + 1][1] = t[3];
                ldsm4(t, bBl + off);
                bl[2 * ntp][0] = t[0]; bl[2 * ntp + 1][0] = t[1];
                bl[2 * ntp][1] = t[2]; bl[2 * ntp + 1][1] = t[3];
            }
#pragma unroll
            for (int mt = 0; mt < 4; mt++) {
                unsigned off = ((m_base + mt * 16 + lrow) * BPAD + kb) * 4;
                unsigned ah[4], al[4];
                ldsm4(ah, bAh + off);
                ldsm4(al, bAl + off);
#pragma unroll
                for (int nt = 0; nt < 4; nt++) {
                    mmabf(acc[mt][nt], ah, bh[nt]);
                    mmabf(acc[mt][nt], ah, bl[nt]);
                    mmabf(acc[mt][nt], al, bh[nt]);
                }
            }
        }
        __syncthreads();
    }

#pragma unroll
    for (int mt = 0; mt < 4; mt++) {
        int row = m0 + m_base + mt * 16 + g;
#pragma unroll
        for (int nt = 0; nt < 4; nt++) {
            int col = n0 + n_base + nt * 8 + 2 * r;
            float2 v0 = {acc[mt][nt][0], acc[mt][nt][1]};
            float2 v1 = {acc[mt][nt][2], acc[mt][nt][3]};
            *(float2*)&C[(size_t)row * N + col] = v0;
            *(float2*)&C[(size_t)(row + 8) * N + col] = v1;
        }
    }
#undef CPA
}

// ---------------------------------------------------------------------------
// RMSNorm + scale + RoPE, writing split-packed hi/lo directly (q/k path).
// ---------------------------------------------------------------------------
__global__ __launch_bounds__(256) void norm_rope_split(const float* __restrict__ buf,
                                                       int nheads,
                                                       const float* __restrict__ scale,
                                                       const int* __restrict__ positions,
                                                       unsigned* __restrict__ hi,
                                                       unsigned* __restrict__ lo) {
    int li = blockIdx.x;
    int h = blockIdx.y;
    int tid = threadIdx.x;
    const float* p = buf + ((size_t)li * nheads + h) * HD;

    float x = p[tid];
    float ss = x * x;
#pragma unroll
    for (int o = 16; o; o >>= 1) ss += __shfl_xor_sync(0xffffffffu, ss, o);
    __shared__ float red[8];
    if ((tid & 31) == 0) red[tid >> 5] = ss;
    __syncthreads();
    float tot = 0.0f;
#pragma unroll
    for (int i = 0; i < 8; i++) tot += red[i];
    float rstd = rsqrtf(tot * (1.0f / 256.0f) + 1e-6f);
    float xn = x * rstd * scale[tid];

    __shared__ float xs[256];
    __shared__ float xr[256];
    xs[tid] = xn;
    __syncthreads();
    if (tid < 128) {
        int pos = positions[li];
        float ts = exp2f(13.287712379549449f * (float)tid * (1.0f / 128.0f));
        float su = (float)pos / ts;
        float s = sinf(su);
        float c = cosf(su);
        float x1 = xs[tid];
        float x2 = xs[tid + 128];
        xr[tid] = x1 * c - x2 * s;
        xr[tid + 128] = x2 * c + x1 * s;
    }
    __syncthreads();
    if (tid < 128) {
        unsigned hh, ll;
        split2(xr[2 * tid], xr[2 * tid + 1], hh, ll);
        size_t o = ((size_t)li * nheads + h) * (HD / 2) + tid;
        hi[o] = hh; lo[o] = ll;
    }
}

// plain RMSNorm (v path), fp32 out
__global__ __launch_bounds__(256) void norm_plain(float* __restrict__ buf, int nheads) {
    int li = blockIdx.x;
    int h = blockIdx.y;
    int tid = threadIdx.x;
    float* p = buf + ((size_t)li * nheads + h) * HD;
    float x = p[tid];
    float ss = x * x;
#pragma unroll
    for (int o = 16; o; o >>= 1) ss += __shfl_xor_sync(0xffffffffu, ss, o);
    __shared__ float red[8];
    if ((tid & 31) == 0) red[tid >> 5] = ss;
    __syncthreads();
    float tot = 0.0f;
#pragma unroll
    for (int i = 0; i < 8; i++) tot += red[i];
    float rstd = rsqrtf(tot * (1.0f / 256.0f) + 1e-6f);
    p[tid] = x * rstd;
}

// ---------------------------------------------------------------------------
// Tensor-core flash attention (compensated bf16, known-good).
// ---------------------------------------------------------------------------
#define AQT 64
#define AKT 32
#define QSTR 132
#define VSTR 20
#define OQH 0
#define OQL (64 * QSTR)
#define OKH (2 * 64 * QSTR)
#define OKL (OKH + 2 * 32 * QSTR)
#define OVH (OKL + 2 * 32 * QSTR)
#define OVL (OVH + 2 * 256 * VSTR)
#define ATTN_SMEM ((OVL + 2 * 256 * VSTR) * 4)

__global__ __launch_bounds__(256) void attn_mma() {
    extern __shared__ unsigned su[];

    int q0 = blockIdx.x * AQT;
    int h = blockIdx.y;
    int kvh = h >> 2;
    int tid = threadIdx.x;
    int lane = tid & 31;
    int w = tid >> 5;
    int g = lane >> 2;
    int r = lane & 3;
    int qgrp = w >> 1;
    int dg = w & 1;

    unsigned sb = (unsigned)__cvta_generic_to_shared(su);

#define CPA1(dstu, src)                                                     \
    asm volatile("cp.async.cg.shared.global [%0], [%1], 16;" ::             \
                 "r"(sb + (dstu) * 4), "l"(src))

    int kt0 = q0 - WIN;
    if (kt0 < 0) kt0 = 0;
    int ktend = q0 + AQT;

#pragma unroll
    for (int i = 0; i < 8; i++) {
        int c = tid + i * 256;
        int row = c >> 5;
        int cl = (c & 31) * 4;
        size_t src = ((size_t)(q0 + row) * NH + h) * (HD / 2) + cl;
        CPA1(OQH + row * QSTR + cl, g_qh + src);
        CPA1(OQL + row * QSTR + cl, g_ql + src);
    }
    {
#pragma unroll
        for (int i = 0; i < 4; i++) {
            int c = tid + i * 256;
            int row = c >> 5;
            int cl = (c & 31) * 4;
            size_t src = ((size_t)(kt0 + row) * NKVH + kvh) * (HD / 2) + cl;
            CPA1(OKH + row * QSTR + cl, g_kh + src);
            CPA1(OKL + row * QSTR + cl, g_kl + src);
        }
#pragma unroll
        for (int i = 0; i < 4; i++) {
            int c = tid + i * 256;
            int row = c >> 2;
            int cl = (c & 3) * 4;
            size_t src = ((size_t)(kvh * HD + row)) * (LQ / 2) + (kt0 >> 1) + cl;
            CPA1(OVH + row * VSTR + cl, g_vth + src);
            CPA1(OVL + row * VSTR + cl, g_vtl + src);
        }
    }
    asm volatile("cp.async.commit_group;");

    float o[16][4];
#pragma unroll
    for (int i = 0; i < 16; i++)
#pragma unroll
        for (int j = 0; j < 4; j++) o[i][j] = 0.0f;
    float m0 = -1e30f, m1 = -1e30f, l0 = 0.0f, l1 = 0.0f;

    int qg0 = q0 + qgrp * 16 + g;
    int qg1 = qg0 + 8;
    int qrow = qgrp * 16 + g;

    int buf = 0;
    for (int kt = kt0; kt < ktend; kt += AKT) {
        bool more = (kt + AKT) < ktend;
        if (more) {
            int nb = buf ^ 1;
            int ktn = kt + AKT;
#pragma unroll
            for (int i = 0; i < 4; i++) {
                int c = tid + i * 256;
                int row = c >> 5;
                int cl = (c & 31) * 4;
                size_t src = ((size_t)(ktn + row) * NKVH + kvh) * (HD / 2) + cl;
                CPA1(OKH + nb * (32 * QSTR) + row * QSTR + cl, g_kh + src);
                CPA1(OKL + nb * (32 * QSTR) + row * QSTR + cl, g_kl + src);
            }
#pragma unroll
            for (int i = 0; i < 4; i++) {
                int c = tid + i * 256;
                int row = c >> 2;
                int cl = (c & 3) * 4;
                size_t src = ((size_t)(kvh * HD + row)) * (LQ / 2) + (ktn >> 1) + cl;
                CPA1(OVH + nb * (256 * VSTR) + row * VSTR + cl, g_vth + src);
                CPA1(OVL + nb * (256 * VSTR) + row * VSTR + cl, g_vtl + src);
            }
            asm volatile("cp.async.commit_group;");
            asm volatile("cp.async.wait_group 1;");
        } else {
            asm volatile("cp.async.wait_group 0;");
        }
        __syncthreads();

        const unsigned* Qhp = su + OQH;
        const unsigned* Qlp = su + OQL;
        const unsigned* Khp = su + OKH + buf * (32 * QSTR);
        const unsigned* Klp = su + OKL + buf * (32 * QSTR);
        const unsigned* Vhp = su + OVH + buf * (256 * VSTR);
        const unsigned* Vlp = su + OVL + buf * (256 * VSTR);

        float s[4][4];
#pragma unroll
        for (int j = 0; j < 4; j++)
#pragma unroll
            for (int e = 0; e < 4; e++) s[j][e] = 0.0f;

#pragma unroll
        for (int k16 = 0; k16 < 16; k16++) {
            int ab = qrow * QSTR + k16 * 8 + r;
            unsigned ah[4], al[4];
            ah[0] = Qhp[ab];
            ah[1] = Qhp[ab + 8 * QSTR];
            ah[2] = Qhp[ab + 4];
            ah[3] = Qhp[ab + 8 * QSTR + 4];
            al[0] = Qlp[ab];
            al[1] = Qlp[ab + 8 * QSTR];
            al[2] = Qlp[ab + 4];
            al[3] = Qlp[ab + 8 * QSTR + 4];
#pragma unroll
            for (int j = 0; j < 4; j++) {
                int bb = (j * 8 + g) * QSTR + k16 * 8 + r;
                unsigned bh[2] = {Khp[bb], Khp[bb + 4]};
                unsigned bl[2] = {Klp[bb], Klp[bb + 4]};
                mmabf(s[j], ah, bh);
                mmabf(s[j], ah, bl);
                mmabf(s[j], al, bh);
            }
        }

        float rm0 = -1e30f, rm1 = -1e30f;
        bool ok[4][4];
#pragma unroll
        for (int j = 0; j < 4; j++) {
            int kg = kt + j * 8 + 2 * r;
            ok[j][0] = (kg <= qg0) && (kg + WIN > qg0);
            ok[j][1] = (kg + 1 <= qg0) && (kg + 1 + WIN > qg0);
            ok[j][2] = (kg <= qg1) && (kg + WIN > qg1);
            ok[j][3] = (kg + 1 <= qg1) && (kg + 1 + WIN > qg1);
            rm0 = fmaxf(rm0, ok[j][0] ? s[j][0] : -1e30f);
            rm0 = fmaxf(rm0, ok[j][1] ? s[j][1] : -1e30f);
            rm1 = fmaxf(rm1, ok[j][2] ? s[j][2] : -1e30f);
            rm1 = fmaxf(rm1, ok[j][3] ? s[j][3] : -1e30f);
        }
        rm0 = fmaxf(rm0, __shfl_xor_sync(0xffffffffu, rm0, 1));
        rm0 = fmaxf(rm0, __shfl_xor_sync(0xffffffffu, rm0, 2));
        rm1 = fmaxf(rm1, __shfl_xor_sync(0xffffffffu, rm1, 1));
        rm1 = fmaxf(rm1, __shfl_xor_sync(0xffffffffu, rm1, 2));

        float mn0 = fmaxf(m0, rm0), mn1 = fmaxf(m1, rm1);
        float e0 = __expf(m0 - mn0), e1 = __expf(m1 - mn1);
        float p[4][4];
        float rs0 = 0.0f, rs1 = 0.0f;
#pragma unroll
        for (int j = 0; j < 4; j++) {
            p[j][0] = ok[j][0] ? __expf(s[j][0] - mn0) : 0.0f;
            p[j][1] = ok[j][1] ? __expf(s[j][1] - mn0) : 0.0f;
            p[j][2] = ok[j][2] ? __expf(s[j][2] - mn1) : 0.0f;
            p[j][3] = ok[j][3] ? __expf(s[j][3] - mn1) : 0.0f;
            rs0 += p[j][0] + p[j][1];
            rs1 += p[j][2] + p[j][3];
        }
        rs0 += __shfl_xor_sync(0xffffffffu, rs0, 1);
        rs0 += __shfl_xor_sync(0xffffffffu, rs0, 2);
        rs1 += __shfl_xor_sync(0xffffffffu, rs1, 1);
        rs1 += __shfl_xor_sync(0xffffffffu, rs1, 2);
        l0 = l0 * e0 + rs0;
        l1 = l1 * e1 + rs1;
        m0 = mn0; m1 = mn1;

#pragma unroll
        for (int jn = 0; jn < 16; jn++) {
            o[jn][0] *= e0; o[jn][1] *= e0;
            o[jn][2] *= e1; o[jn][3] *= e1;
        }

        unsigned ph[2][4], pl[2][4];
#pragma unroll
        for (int kh2 = 0; kh2 < 2; kh2++) {
            int j0 = kh2 * 2;
            split2(p[j0][0], p[j0][1], ph[kh2][0], pl[kh2][0]);
            split2(p[j0][2], p[j0][3], ph[kh2][1], pl[kh2][1]);
            split2(p[j0 + 1][0], p[j0 + 1][1], ph[kh2][2], pl[kh2][2]);
            split2(p[j0 + 1][2], p[j0 + 1][3], ph[kh2][3], pl[kh2][3]);
        }

#pragma unroll
        for (int jn = 0; jn < 16; jn++) {
            int d = dg * 128 + jn * 8 + g;
#pragma unroll
            for (int kh2 = 0; kh2 < 2; kh2++) {
                int vb = d * VSTR + kh2 * 8 + r;
                unsigned bh[2] = {Vhp[vb], Vhp[vb + 4]};
                unsigned bl[2] = {Vlp[vb], Vlp[vb + 4]};
                mmabf(o[jn], ph[kh2], bh);
                mmabf(o[jn], ph[kh2], bl);
                mmabf(o[jn], pl[kh2], bh);
            }
        }
        __syncthreads();
        buf ^= 1;
    }

    float inv0 = 1.0f / l0, inv1 = 1.0f / l1;
    int row0 = q0 + qgrp * 16 + g;
#pragma unroll
    for (int jn = 0; jn < 16; jn++) {
        int col = dg * 128 + jn * 8 + 2 * r;
        float2 v0 = {o[jn][0] * inv0, o[jn][1] * inv0};
        float2 v1 = {o[jn][2] * inv1, o[jn][3] * inv1};
        *(float2*)&g_attn[((size_t)row0 * NH + h) * HD + col] = v0;
        *(float2*)&g_attn[((size_t)(row0 + 8) * NH + h) * HD + col] = v1;
    }
#undef CPA1
}

// ---------------------------------------------------------------------------
extern "C" void kernel_launch(void* const* d_in, const int* in_sizes, int n_in,
                              void* d_out, int out_size) {
    const float* x = (const float*)d_in[0];
    const int* positions = (const int*)d_in[1];
    const float* Wq = (const float*)d_in[2];
    const float* Wk = (const float*)d_in[3];
    const float* Wv = (const float*)d_in[4];
    const float* Wo = (const float*)d_in[5];
    const float* q_scale = (const float*)d_in[6];
    const float* k_scale = (const float*)d_in[7];
    float* out = (float*)d_out;

    float *qb, *kb, *vb, *ab;
    unsigned *xh, *xl, *ah, *al;
    unsigned *wqh, *wql, *wkh, *wkl, *wvh, *wvl, *woh, *wol;
    unsigned *qh, *ql, *kh, *kl;
    cudaGetSymbolAddress((void**)&qb, g_q);
    cudaGetSymbolAddress((void**)&kb, g_k);
    cudaGetSymbolAddress((void**)&vb, g_v);
    cudaGetSymbolAddress((void**)&ab, g_attn);
    cudaGetSymbolAddress((void**)&xh, g_xh);
    cudaGetSymbolAddress((void**)&xl, g_xl);
    cudaGetSymbolAddress((void**)&ah, g_ah);
    cudaGetSymbolAddress((void**)&al, g_al);
    cudaGetSymbolAddress((void**)&wqh, g_wqh);
    cudaGetSymbolAddress((void**)&wql, g_wql);
    cudaGetSymbolAddress((void**)&wkh, g_wkh);
    cudaGetSymbolAddress((void**)&wkl, g_wkl);
    cudaGetSymbolAddress((void**)&wvh, g_wvh);
    cudaGetSymbolAddress((void**)&wvl, g_wvl);
    cudaGetSymbolAddress((void**)&woh, g_woh);
    cudaGetSymbolAddress((void**)&wol, g_wol);
    cudaGetSymbolAddress((void**)&qh, g_qh);
    cudaGetSymbolAddress((void**)&ql, g_ql);
    cudaGetSymbolAddress((void**)&kh, g_kh);
    cudaGetSymbolAddress((void**)&kl, g_kl);

    cudaFuncSetAttribute(bgemm, cudaFuncAttributeMaxDynamicSharedMemorySize,
                         8 * SMBUF * 4);
    cudaFuncSetAttribute(attn_mma, cudaFuncAttributeMaxDynamicSharedMemorySize,
                         ATTN_SMEM);

    dim3 blk(256);

    {
        int np = LQ * DIM / 2;
        splitpack<<<(np + 255) / 256, blk>>>(x, xh, xl, np);
        int tq = (NH * HD) * (DIM / 2);
        wsplit<<<(tq + 255) / 256, blk>>>(Wq, wqh, wql, DIM, NH * HD);
        int tk = (NKVH * HD) * (DIM / 2);
        wsplit<<<(tk + 255) / 256, blk>>>(Wk, wkh, wkl, DIM, NKVH * HD);
        wsplit<<<(tk + 255) / 256, blk>>>(Wv, wvh, wvl, DIM, NKVH * HD);
        int to = DIM * ((NH * HD) / 2);
        wsplit<<<(to + 255) / 256, blk>>>(Wo, woh, wol, NH * HD, DIM);
    }

    bgemm<<<dim3(24, LQ / 128), blk, 8 * SMBUF * 4>>>(
        xh, xl, DIM,
        wqh, wql, qb, NH * HD, 16,
        wkh, wkl, kb, NKVH * HD, 4,
        wvh, wvl, vb, NKVH * HD);

    // norm + rope + split fused (q, k); v plain fp32 norm then transpose-split
    norm_rope_split<<<dim3(LQ, NH), blk>>>(qb, NH, q_scale, positions, qh, ql);
    norm_rope_split<<<dim3(LQ, NKVH), blk>>>(kb, NKVH, k_scale, positions, kh, kl);
    norm_plain<<<dim3(LQ, NKVH), blk>>>(vb, NKVH);
    vtsplit<<<dim3(LQ / 64, HD / 64, NKVH), blk>>>();

    attn_mma<<<dim3(LQ / AQT, NH), blk, ATTN_SMEM>>>();

    {
        int np = LQ * (NH * HD) / 2;
        splitpack<<<(np + 255) / 256, blk>>>(ab, ah, al, np);
    }
    bgemm<<<dim3(16, LQ / 128), blk, 8 * SMBUF * 4>>>(
        ah, al, NH * HD,
        woh, wol, out, DIM, 16,
        (const unsigned*)nullptr, (const unsigned*)nullptr, (float*)nullptr, 0, 0,
        (const unsigned*)nullptr, (const unsigned*)nullptr, (float*)nullptr, 0);
}